// round 16
// baseline (speedup 1.0000x reference)
#include <cuda_runtime.h>
#include <cuda_fp16.h>

// Problem constants
#define T_LEN 512
#define B_SZ  32
#define D_IN  512
#define H_SZ  1024
#define G_SZ  4096   // 4*H
#define NCTA  128    // persist CTAs: 64 gate-tiles x 2 dirs (+20 GEMM CTAs)

// ---------------------------------------------------------------------------
// Scratch (allocation-free __device__ globals)
// g_xg     : [dir][s][b][g'] fp32 input contributions, g' = 4j+gate (i,f,g,o)
// g_WhhB   : [dir][ct64][nt8][kk64][L32] uint2 fp16 mma B frags of Whh
// g_WihB   : [dir][ntile512][kk32][L32] uint2 fp16 B frags of Wih
// g_xAH    : [rt1024][kk32][L32] uint4 fp16 A frags of x
// g_hfragH : [buf2][dir2][mt2][kk64][lane32][reg4] unsigned fp16 A frags of h
// g_bsum   : [dir][g'] permuted bias sums
// g_arr    : per-direction grid barrier: [dir][q4] spread counters
// g_xgready: [dir][mcg8] producer->consumer flags (target 32 arrivals each)
// ---------------------------------------------------------------------------
__device__ float g_xg[(size_t)2 * T_LEN * B_SZ * G_SZ];     // 536 MB
__device__ uint2 g_WhhB[(size_t)2 * 64 * 8 * 64 * 32];      // 16.8 MB
__device__ uint2 g_WihB[(size_t)2 * 512 * 32 * 32];         // 8.4 MB
__device__ uint4 g_xAH[(size_t)1024 * 32 * 32];             // 16.8 MB
__device__ unsigned g_hfragH[2 * 2 * 2 * 64 * 32 * 4];      // 0.5 MB
__device__ float g_bsum[2 * G_SZ];
__device__ unsigned g_arr[2 * 4 * 32];                      // spread counters
__device__ unsigned g_xgready[2 * 8 * 32];                  // spread flags

// ---------------------------------------------------------------------------
__device__ __forceinline__ unsigned pack_h2(float a, float b) {
    __half2 h;
    h.x = __float2half_rn(a); h.y = __float2half_rn(b);
    return *(unsigned*)&h;
}
__device__ __forceinline__ float sigm(float x) {
    return 1.0f / (1.0f + __expf(-x));
}
__device__ __forceinline__ float ftanh(float x) {
    return __fmaf_rn(2.0f, sigm(2.0f * x), -1.0f);
}

// ---------------------------------------------------------------------------
// Fused prep kernel (one launch): W_hh pack, W_ih pack, x pack, bias sums,
// barrier + flag init, via block-range dispatch.
// ---------------------------------------------------------------------------
__global__ void prep_kernel(const float* __restrict__ Wf_hh,
                            const float* __restrict__ Wb_hh,
                            const float* __restrict__ Wf_ih,
                            const float* __restrict__ Wb_ih,
                            const float* __restrict__ bfi,
                            const float* __restrict__ bfh,
                            const float* __restrict__ bbi,
                            const float* __restrict__ bbh,
                            const float* __restrict__ x)
{
    const unsigned bid = blockIdx.x;
    const int tid = threadIdx.x;

    if (bid < 8192u) {
        // ---- W_hh pack: idx = ((((dir*64+ct)*8+nt)*64+kk)*32+L) ----
        const unsigned idx = bid * 256 + tid;
        const int L   = idx & 31;
        const int kk  = (idx >> 5) & 63;
        const int nt  = (idx >> 11) & 7;
        const int ct  = (idx >> 14) & 63;
        const int dir = idx >> 20;
        const float* __restrict__ W = dir ? Wb_hh : Wf_hh;
        const int gp = ((ct << 3) + nt) * 8 + (L >> 2);
        const float* row = W + (size_t)((gp & 3) * H_SZ + (gp >> 2)) * H_SZ;
        const int t2 = (L & 3) * 2;
        g_WhhB[idx] = make_uint2(
            pack_h2(row[kk * 16 + t2],     row[kk * 16 + t2 + 1]),
            pack_h2(row[kk * 16 + t2 + 8], row[kk * 16 + t2 + 9]));
    } else if (bid < 12288u) {
        // ---- W_ih pack: idx = (((dir*512+ntile)*32+kk)*32+L) ----
        const unsigned idx = (bid - 8192u) * 256 + tid;
        const int L   = idx & 31;
        const int kk  = (idx >> 5) & 31;
        const int ntl = (idx >> 10) & 511;
        const int dir = idx >> 19;
        const float* __restrict__ W = dir ? Wb_ih : Wf_ih;
        const int gp = (ntl << 3) + (L >> 2);
        const float* row = W + (size_t)((gp & 3) * H_SZ + (gp >> 2)) * D_IN;
        const int k0 = kk * 16 + (L & 3) * 2;
        g_WihB[idx] = make_uint2(pack_h2(row[k0],     row[k0 + 1]),
                                 pack_h2(row[k0 + 8], row[k0 + 9]));
    } else if (bid < 16384u) {
        // ---- x pack (physical-time row order) ----
        const unsigned idx = (bid - 12288u) * 256 + tid;
        const int L  = idx & 31;
        const int kk = (idx >> 5) & 31;
        const int rt = idx >> 10;
        const int r0 = rt * 16 + (L >> 2);
        const int r1 = r0 + 8;
        const int k0 = kk * 16 + (L & 3) * 2;
        const float* x0 = x + ((size_t)(r0 & 31) * T_LEN + (r0 >> 5)) * D_IN;
        const float* x1 = x + ((size_t)(r1 & 31) * T_LEN + (r1 >> 5)) * D_IN;
        uint4 p;
        p.x = pack_h2(x0[k0],     x0[k0 + 1]);
        p.y = pack_h2(x1[k0],     x1[k0 + 1]);
        p.z = pack_h2(x0[k0 + 8], x0[k0 + 9]);
        p.w = pack_h2(x1[k0 + 8], x1[k0 + 9]);
        g_xAH[idx] = p;
    } else if (bid < 16416u) {
        // ---- bias sums ----
        const unsigned idx = (bid - 16384u) * 256 + tid;
        const int g = idx & (G_SZ - 1);
        const int dir = idx >> 12;
        const int orig = (g & 3) * H_SZ + (g >> 2);
        g_bsum[idx] = dir ? (bbi[orig] + bbh[orig]) : (bfi[orig] + bfh[orig]);
    } else {
        // ---- barrier + flag init ----
        if (tid < 2 * 4 * 32) g_arr[tid] = 0u;
        for (int i = tid; i < 2 * 8 * 32; i += 256) g_xgready[i] = 0u;
    }
}

// ---------------------------------------------------------------------------
__device__ __forceinline__ void mma_f16(float* c,
                                        unsigned a0, unsigned a1,
                                        unsigned a2, unsigned a3,
                                        unsigned b0, unsigned b1) {
    asm volatile(
        "mma.sync.aligned.m16n8k16.row.col.f32.f16.f16.f32 "
        "{%0,%1,%2,%3}, {%4,%5,%6,%7}, {%8,%9}, {%0,%1,%2,%3};"
        : "+f"(c[0]), "+f"(c[1]), "+f"(c[2]), "+f"(c[3])
        : "r"(a0), "r"(a1), "r"(a2), "r"(a3), "r"(b0), "r"(b1));
}

// ---------------------------------------------------------------------------
// Fused persistent kernel, grid 148:
//   CTAs [0,128)   — recurrence (unchanged R15 champion core)
//   CTAs [128,148) — input-GEMM producer role on the otherwise-idle SMs:
//       mcg-outer (s-order) / pair-inner; per (pair, mcg): stage B tile to
//       smem, compute 16 M-tiles (identical math to R15 GEMM), then
//       release-arrive on g_xgready[dir][mcg] (target 32 = all n0t pairs).
//   Consumers poll the flag only at 64-step block boundaries (8x/kernel)
//   before prefetching xg. Producers never wait on consumers; all consumer
//   spins bounded -> no hang possible.
// ---------------------------------------------------------------------------
#define WS_U2   16384                        // 8*64*32 uint2 (131072 B)
#define PS_OFF  (WS_U2 * 2)
#define PSW     2432                         // 32 rows * stride 76
#define SMEM_BYTES (WS_U2 * 8 + 8 * PSW * 4) // 208896 (GEMM role uses 131072)

__global__ __launch_bounds__(256, 1)
void lstm_persist_kernel(float* __restrict__ out, int write_hc)
{
    extern __shared__ float sm[];
    const int tid = threadIdx.x;
    const int w   = tid >> 5;
    const int L   = tid & 31;
    unsigned spin_limit = 2000000u;          // bounded: ~1.2s worst case

    // =====================================================================
    // Producer role: input GEMM on the 20 SMs the recurrence doesn't use.
    // =====================================================================
    if (blockIdx.x >= NCTA) {
        uint2* sB = (uint2*)sm;              // [ntl16][kk32][L32], 131072 B
        const int g  = blockIdx.x - NCTA;    // 0..19
        const int bh = w & 1;

        for (int mcg = 0; mcg < 8; mcg++) {
            for (int p = g; p < 64; p += 20) {
                const int dir = p >> 5;
                const int n0t = (p & 31) * 16;

                // stage B tile
                const uint2* src = g_WihB + ((size_t)dir * 512 + n0t) * (32 * 32);
                for (int i = tid; i < 16 * 32 * 32; i += 256) sB[i] = src[i];
                __syncthreads();

                const int gb = n0t * 8 + (L & 3) * 2;
                const float* bs = g_bsum + dir * G_SZ;

                for (int it = 0; it < 16; it++) {
                    const int mc = mcg * 16 + it;
                    const int sw = mc * 4 + (w >> 1);
                    const int tp = dir ? (T_LEN - 1 - sw) : sw;
                    const uint4* __restrict__ aptr =
                        g_xAH + (size_t)(tp * 2 + bh) * 1024 + L;

                    float acc[16][4];
                    #pragma unroll
                    for (int nt = 0; nt < 16; nt++)
                        #pragma unroll
                        for (int i = 0; i < 4; i++) acc[nt][i] = 0.0f;

                    uint4 A = aptr[0];
                    for (int kk = 0; kk < 32; kk++) {
                        const uint4 C = A;
                        if (kk < 31) A = aptr[(kk + 1) * 32];
                        #pragma unroll
                        for (int nt = 0; nt < 16; nt++) {
                            const uint2 bb = sB[(nt * 32 + kk) * 32 + L];
                            mma_f16(acc[nt], C.x, C.y, C.z, C.w, bb.x, bb.y);
                        }
                    }

                    const int b0 = bh * 16 + (L >> 2);
                    const int b1 = b0 + 8;
                    float* xg0 = g_xg + (((size_t)dir * T_LEN + sw) * B_SZ + b0) * G_SZ;
                    float* xg1 = g_xg + (((size_t)dir * T_LEN + sw) * B_SZ + b1) * G_SZ;
                    #pragma unroll
                    for (int nt = 0; nt < 16; nt++) {
                        const int gg = gb + nt * 8;
                        const float2 bias = *(const float2*)(bs + gg);
                        *(float2*)(xg0 + gg) = make_float2(acc[nt][0] + bias.x,
                                                           acc[nt][1] + bias.y);
                        *(float2*)(xg1 + gg) = make_float2(acc[nt][2] + bias.x,
                                                           acc[nt][3] + bias.y);
                    }
                }

                __syncthreads();   // all stores issued; also guards sB restage
                if (tid == 0) {
                    unsigned* f = &g_xgready[(dir * 8 + mcg) * 32];
                    asm volatile("red.release.gpu.global.add.u32 [%0], 1;"
                                 :: "l"(f) : "memory");
                }
            }
        }
        return;
    }

    // =====================================================================
    // Consumer role: recurrence (R15 champion core + xg-block flag waits)
    // =====================================================================
    uint2* ws = (uint2*)sm;
    float* ps = sm + PS_OFF;

    const int dir = blockIdx.x >> 6;
    const int ct  = blockIdx.x & 63;

    {   // load W_hh fp16 slice into smem (once)
        const uint2* src = g_WhhB + ((size_t)(dir * 64 + ct) << 14);
        for (int i = tid; i < WS_U2; i += 256) ws[i] = src[i];
    }

    int bb[2], ul[2];
    #pragma unroll
    for (int p = 0; p < 2; p++) {
        const int cid = tid + (p << 8);
        bb[p] = cid >> 4;
        ul[p] = cid & 15;
    }
    float creg[2] = {0.0f, 0.0f};

    const size_t OUT_HC0 = (size_t)B_SZ * T_LEN * 2 * H_SZ;
    const size_t OUT_HC1 = OUT_HC0 + (size_t)B_SZ * 2 * H_SZ;

    __syncthreads();

    // wait for xg block 0 of this dir, then prefetch xg for s=0
    if (tid == 0) {
        unsigned vv, it = 0;
        for (;;) {
            asm volatile("ld.acquire.gpu.global.u32 %0, [%1];"
                         : "=r"(vv) : "l"(&g_xgready[(dir * 8) * 32]) : "memory");
            if (vv >= 32u) break;
            if (++it >= spin_limit) { spin_limit = 0; break; }
        }
    }
    __syncthreads();

    float4 xgn[2];
    #pragma unroll
    for (int p = 0; p < 2; p++)
        xgn[p] = __ldcg((const float4*)(g_xg
                 + ((size_t)dir * T_LEN * B_SZ + bb[p]) * G_SZ
                 + (ct << 6) + (ul[p] << 2)));

    for (int s = 0; s < T_LEN; s++) {
        const int buf  = s & 1;
        const int nbuf = buf ^ 1;

        const float4 xgv0 = xgn[0];
        const float4 xgv1 = xgn[1];

        if (s > 0) {
            float acc[2][8][4];
            #pragma unroll
            for (int mt = 0; mt < 2; mt++)
                #pragma unroll
                for (int nt = 0; nt < 8; nt++)
                    #pragma unroll
                    for (int i = 0; i < 4; i++) acc[mt][nt][i] = 0.0f;

            const uint4* afb = (const uint4*)g_hfragH
                               + ((size_t)(buf * 2 + dir) * 2) * (64 * 32);
            const int kk0 = w << 3;

            // depth-2 pipelined A-fragment loads
            uint4 A[2][2];   // [stage][mt]
            #pragma unroll
            for (int st = 0; st < 2; st++)
                #pragma unroll
                for (int mt = 0; mt < 2; mt++)
                    A[st][mt] = __ldcg(afb + ((size_t)mt * 64 + kk0 + st) * 32 + L);

            #pragma unroll
            for (int i = 0; i < 8; i++) {
                const int st = i & 1;
                const int kk = kk0 + i;
                #pragma unroll
                for (int nt = 0; nt < 8; nt++) {
                    const uint2 wh = ws[((nt << 6) + kk) * 32 + L];
                    #pragma unroll
                    for (int mt = 0; mt < 2; mt++)
                        mma_f16(acc[mt][nt], A[st][mt].x, A[st][mt].y,
                                A[st][mt].z, A[st][mt].w, wh.x, wh.y);
                }
                if (i + 2 < 8) {
                    #pragma unroll
                    for (int mt = 0; mt < 2; mt++)
                        A[st][mt] = __ldcg(afb + ((size_t)mt * 64 + kk0 + i + 2) * 32
                                           + L);
                }
            }

            float* psw = ps + w * PSW;
            const int r  = L >> 2;
            const int g2 = (L & 3) * 2;
            #pragma unroll
            for (int mt = 0; mt < 2; mt++)
                #pragma unroll
                for (int nt = 0; nt < 8; nt++) {
                    const int row = mt * 16 + r;
                    const int g   = nt * 8 + g2;
                    *(float2*)&psw[row * 76 + g] =
                        make_float2(acc[mt][nt][0], acc[mt][nt][1]);
                    *(float2*)&psw[(row + 8) * 76 + g] =
                        make_float2(acc[mt][nt][2], acc[mt][nt][3]);
                }
        }
        __syncthreads();

        const int tphys = dir ? (T_LEN - 1 - s) : s;
        #pragma unroll
        for (int p = 0; p < 2; p++) {
            const int b = bb[p];
            const int u = ul[p];
            const int j = (ct << 4) + u;
            const float4 xgv = p ? xgv1 : xgv0;

            float4 v = make_float4(0.f, 0.f, 0.f, 0.f);
            if (s > 0) {
                #pragma unroll
                for (int ww = 0; ww < 8; ww++) {
                    const float4 q = *(const float4*)&ps[ww * PSW + b * 76 + u * 4];
                    v.x += q.x; v.y += q.y; v.z += q.z; v.w += q.w;
                }
            }

            const float iv = sigm(v.x + xgv.x);
            const float fv = sigm(v.y + xgv.y);
            const float gv = ftanh(v.z + xgv.z);
            const float ov = sigm(v.w + xgv.w);
            const float cc = fv * creg[p] + iv * gv;
            creg[p] = cc;
            const float h = ov * ftanh(cc);

            out[((size_t)b * T_LEN + tphys) * (2 * H_SZ) + (size_t)dir * H_SZ + j] = h;
            if (write_hc && s == T_LEN - 1) {
                out[OUT_HC0 + ((size_t)b * 2 + dir) * H_SZ + j] = h;
                out[OUT_HC1 + ((size_t)b * 2 + dir) * H_SZ + j] = cc;
            }

            const float hn = __shfl_down_sync(0xffffffffu, h, 1);
            if ((u & 1) == 0) {
                const unsigned hi = pack_h2(h, hn);
                const int mt    = b >> 4;
                const int rowin = b & 15;
                const int reg   = (rowin >> 3) + ((u >> 3) << 1);
                const int lane2 = (rowin & 7) * 4 + ((u & 7) >> 1);
                g_hfragH[(((size_t)(nbuf * 2 + dir) * 2 + mt) * 64 + ct) * 128
                         + lane2 * 4 + reg] = hi;
            }
        }

        // prefetch xg for step s+1 BEFORE the barrier (in flight during wait);
        // at 64-step block boundaries, first wait for the producer flag.
        if (s + 1 < T_LEN) {
            if (((s + 1) & 63) == 0) {
                if (tid == 0) {
                    const int blk = (s + 1) >> 6;
                    unsigned vv, it = 0;
                    for (;;) {
                        asm volatile("ld.acquire.gpu.global.u32 %0, [%1];"
                                     : "=r"(vv)
                                     : "l"(&g_xgready[(dir * 8 + blk) * 32])
                                     : "memory");
                        if (vv >= 32u) break;
                        if (++it >= spin_limit) { spin_limit = 0; break; }
                    }
                }
                __syncthreads();
            }
            const size_t xgb1 = ((size_t)dir * T_LEN + (s + 1)) * B_SZ * G_SZ;
            #pragma unroll
            for (int p = 0; p < 2; p++)
                xgn[p] = __ldcg((const float4*)(g_xg + xgb1
                         + (size_t)bb[p] * G_SZ + (ct << 6) + (ul[p] << 2)));
        }

        // flat per-direction grid barrier (64 CTAs, 4 spread counters)
        __syncthreads();
        if (tid == 0) {
            unsigned* ctr = &g_arr[(dir * 4 + (ct & 3)) * 32];
            asm volatile("red.release.gpu.global.add.u32 [%0], 1;"
                         :: "l"(ctr) : "memory");
            const unsigned tgt = (unsigned)(s + 1) * 16;
            unsigned it = 0;
            for (;;) {
                unsigned done = 1;
                #pragma unroll
                for (int q = 0; q < 4; q++) {
                    unsigned vv;
                    asm volatile("ld.acquire.gpu.global.u32 %0, [%1];"
                                 : "=r"(vv) : "l"(&g_arr[(dir * 4 + q) * 32])
                                 : "memory");
                    done &= (unsigned)(vv >= tgt);
                }
                if (done) break;
                if (++it >= spin_limit) { spin_limit = 0; break; }
            }
        }
        __syncthreads();
    }
}

// ---------------------------------------------------------------------------
extern "C" void kernel_launch(void* const* d_in, const int* in_sizes, int n_in,
                              void* d_out, int out_size)
{
    const float* x     = (const float*)d_in[0];
    const float* Wf_ih = (const float*)d_in[1];
    const float* Wf_hh = (const float*)d_in[2];
    const float* bf_ih = (const float*)d_in[3];
    const float* bf_hh = (const float*)d_in[4];
    const float* Wb_ih = (const float*)d_in[5];
    const float* Wb_hh = (const float*)d_in[6];
    const float* bb_ih = (const float*)d_in[7];
    const float* bb_hh = (const float*)d_in[8];
    float* out = (float*)d_out;

    static int smem_set = 0;
    if (!smem_set) {
        cudaFuncSetAttribute(lstm_persist_kernel,
                             cudaFuncAttributeMaxDynamicSharedMemorySize,
                             SMEM_BYTES);
        smem_set = 1;
    }

    // one fused prep launch: W packs + x pack + bias sums + flag/barrier init
    prep_kernel<<<16417, 256>>>(Wf_hh, Wb_hh, Wf_ih, Wb_ih,
                                bf_ih, bf_hh, bb_ih, bb_hh, x);

    const long long full = (long long)B_SZ * T_LEN * 2 * H_SZ
                         + 2LL * B_SZ * 2 * H_SZ;
    const int write_hc = ((long long)out_size >= full) ? 1 : 0;

    // fused producer(20 CTAs) + consumer(128 CTAs) persistent kernel
    lstm_persist_kernel<<<NCTA + 20, 256, SMEM_BYTES>>>(out, write_hc);
}

// round 17
// speedup vs baseline: 1.8372x; 1.8372x over previous
#include <cuda_runtime.h>
#include <cuda_fp16.h>

// Problem constants
#define T_LEN 512
#define B_SZ  32
#define D_IN  512
#define H_SZ  1024
#define G_SZ  4096   // 4*H
#define NCTA  128    // persistent grid: 64 gate-tiles x 2 dirs

// ---------------------------------------------------------------------------
// Scratch (allocation-free __device__ globals)
// g_xg    : [dir][s][b][g'] fp32 input contributions, g' = 4j+gate (i,f,g,o)
// g_WhhB  : [dir][ct64][nt8][kk64][L32] uint2 fp16 mma B frags of Whh
// g_WihB  : [dir][ntile512][kk32][L32] uint2 fp16 B frags of Wih
// g_xAH   : [rt1024][kk32][L32] uint4 fp16 A frags of x
// g_hfragH: [buf2][dir2][mt2][kk64][lane32][reg4] unsigned fp16 A frags of h
// g_bsum  : [dir][g'] permuted bias sums
// g_arr   : per-direction grid barrier: [dir][q4] spread counters
// ---------------------------------------------------------------------------
__device__ float g_xg[(size_t)2 * T_LEN * B_SZ * G_SZ];     // 536 MB
__device__ uint2 g_WhhB[(size_t)2 * 64 * 8 * 64 * 32];      // 16.8 MB
__device__ uint2 g_WihB[(size_t)2 * 512 * 32 * 32];         // 8.4 MB
__device__ uint4 g_xAH[(size_t)1024 * 32 * 32];             // 16.8 MB
__device__ unsigned g_hfragH[2 * 2 * 2 * 64 * 32 * 4];      // 0.5 MB
__device__ float g_bsum[2 * G_SZ];
__device__ unsigned g_arr[2 * 4 * 32];                      // spread counters

// ---------------------------------------------------------------------------
__device__ __forceinline__ unsigned pack_h2(float a, float b) {
    __half2 h;
    h.x = __float2half_rn(a); h.y = __float2half_rn(b);
    return *(unsigned*)&h;
}
__device__ __forceinline__ float sigm(float x) {
    return 1.0f / (1.0f + __expf(-x));
}
__device__ __forceinline__ float ftanh(float x) {
    return __fmaf_rn(2.0f, sigm(2.0f * x), -1.0f);
}

// ---------------------------------------------------------------------------
// Fused prep kernel (one launch): W_hh pack, W_ih pack, x pack, bias sums,
// barrier init, via block-range dispatch.
// ---------------------------------------------------------------------------
__global__ void prep_kernel(const float* __restrict__ Wf_hh,
                            const float* __restrict__ Wb_hh,
                            const float* __restrict__ Wf_ih,
                            const float* __restrict__ Wb_ih,
                            const float* __restrict__ bfi,
                            const float* __restrict__ bfh,
                            const float* __restrict__ bbi,
                            const float* __restrict__ bbh,
                            const float* __restrict__ x)
{
    const unsigned bid = blockIdx.x;
    const int tid = threadIdx.x;

    if (bid < 8192u) {
        // ---- W_hh pack: idx = ((((dir*64+ct)*8+nt)*64+kk)*32+L) ----
        const unsigned idx = bid * 256 + tid;
        const int L   = idx & 31;
        const int kk  = (idx >> 5) & 63;
        const int nt  = (idx >> 11) & 7;
        const int ct  = (idx >> 14) & 63;
        const int dir = idx >> 20;
        const float* __restrict__ W = dir ? Wb_hh : Wf_hh;
        const int gp = ((ct << 3) + nt) * 8 + (L >> 2);
        const float* row = W + (size_t)((gp & 3) * H_SZ + (gp >> 2)) * H_SZ;
        const int t2 = (L & 3) * 2;
        g_WhhB[idx] = make_uint2(
            pack_h2(row[kk * 16 + t2],     row[kk * 16 + t2 + 1]),
            pack_h2(row[kk * 16 + t2 + 8], row[kk * 16 + t2 + 9]));
    } else if (bid < 12288u) {
        // ---- W_ih pack: idx = (((dir*512+ntile)*32+kk)*32+L) ----
        const unsigned idx = (bid - 8192u) * 256 + tid;
        const int L   = idx & 31;
        const int kk  = (idx >> 5) & 31;
        const int ntl = (idx >> 10) & 511;
        const int dir = idx >> 19;
        const float* __restrict__ W = dir ? Wb_ih : Wf_ih;
        const int gp = (ntl << 3) + (L >> 2);
        const float* row = W + (size_t)((gp & 3) * H_SZ + (gp >> 2)) * D_IN;
        const int k0 = kk * 16 + (L & 3) * 2;
        g_WihB[idx] = make_uint2(pack_h2(row[k0],     row[k0 + 1]),
                                 pack_h2(row[k0 + 8], row[k0 + 9]));
    } else if (bid < 16384u) {
        // ---- x pack (physical-time row order) ----
        const unsigned idx = (bid - 12288u) * 256 + tid;
        const int L  = idx & 31;
        const int kk = (idx >> 5) & 31;
        const int rt = idx >> 10;
        const int r0 = rt * 16 + (L >> 2);
        const int r1 = r0 + 8;
        const int k0 = kk * 16 + (L & 3) * 2;
        const float* x0 = x + ((size_t)(r0 & 31) * T_LEN + (r0 >> 5)) * D_IN;
        const float* x1 = x + ((size_t)(r1 & 31) * T_LEN + (r1 >> 5)) * D_IN;
        uint4 p;
        p.x = pack_h2(x0[k0],     x0[k0 + 1]);
        p.y = pack_h2(x1[k0],     x1[k0 + 1]);
        p.z = pack_h2(x0[k0 + 8], x0[k0 + 9]);
        p.w = pack_h2(x1[k0 + 8], x1[k0 + 9]);
        g_xAH[idx] = p;
    } else if (bid < 16416u) {
        // ---- bias sums ----
        const unsigned idx = (bid - 16384u) * 256 + tid;
        const int g = idx & (G_SZ - 1);
        const int dir = idx >> 12;
        const int orig = (g & 3) * H_SZ + (g >> 2);
        g_bsum[idx] = dir ? (bbi[orig] + bbh[orig]) : (bfi[orig] + bfh[orig]);
    } else {
        // ---- barrier init ----
        if (tid < 2 * 4 * 32) g_arr[tid] = 0u;
    }
}

// ---------------------------------------------------------------------------
__device__ __forceinline__ void mma_f16(float* c,
                                        unsigned a0, unsigned a1,
                                        unsigned a2, unsigned a3,
                                        unsigned b0, unsigned b1) {
    asm volatile(
        "mma.sync.aligned.m16n8k16.row.col.f32.f16.f16.f32 "
        "{%0,%1,%2,%3}, {%4,%5,%6,%7}, {%8,%9}, {%0,%1,%2,%3};"
        : "+f"(c[0]), "+f"(c[1]), "+f"(c[2]), "+f"(c[3])
        : "r"(a0), "r"(a1), "r"(a2), "r"(a3), "r"(b0), "r"(b1));
}

// ---------------------------------------------------------------------------
// Tensor-core input GEMM, single-pass fp16, M-looped, 2 CTAs/SM:
// grid (8,64,2) = 1024 CTAs; each stages a 64KB B tile (8 ntl) once and
// loops 16 M-tiles. 2 co-resident CTAs/SM double the warps hiding A-load
// latency vs the 1-CTA/SM R15 version.
// ---------------------------------------------------------------------------
#define GEMM_SMEM (8 * 32 * 32 * 8)    // 65536

__global__ __launch_bounds__(256, 2)
void input_gemm_mma_kernel()
{
    extern __shared__ uint2 sB[];      // [ntl8][kk32][L32]
    const int dir = blockIdx.z;
    const int mcg = blockIdx.x;        // M-tile group: mc in [mcg*16, mcg*16+16)
    const int n0t = blockIdx.y * 8;    // base ntile (8 cols each)
    const int tid = threadIdx.x;
    const int w   = tid >> 5;
    const int L   = tid & 31;

    {   // stage B tile once
        const uint2* src = g_WihB + ((size_t)dir * 512 + n0t) * (32 * 32);
        for (int i = tid; i < 8 * 32 * 32; i += 256) sB[i] = src[i];
    }
    __syncthreads();

    const int bh = w & 1;
    const int gb = n0t * 8 + (L & 3) * 2;
    const float* bs = g_bsum + dir * G_SZ;

    for (int it = 0; it < 16; it++) {
        const int mc = mcg * 16 + it;
        const int sw = mc * 4 + (w >> 1);
        const int tp = dir ? (T_LEN - 1 - sw) : sw;
        const uint4* __restrict__ aptr = g_xAH + (size_t)(tp * 2 + bh) * 1024 + L;

        float acc[8][4];
        #pragma unroll
        for (int nt = 0; nt < 8; nt++)
            #pragma unroll
            for (int i = 0; i < 4; i++) acc[nt][i] = 0.0f;

        uint4 A = aptr[0];
        for (int kk = 0; kk < 32; kk++) {
            const uint4 C = A;
            if (kk < 31) A = aptr[(kk + 1) * 32];
            #pragma unroll
            for (int nt = 0; nt < 8; nt++) {
                const uint2 bb = sB[(nt * 32 + kk) * 32 + L];
                mma_f16(acc[nt], C.x, C.y, C.z, C.w, bb.x, bb.y);
            }
        }

        const int b0 = bh * 16 + (L >> 2);
        const int b1 = b0 + 8;
        float* xg0 = g_xg + (((size_t)dir * T_LEN + sw) * B_SZ + b0) * G_SZ;
        float* xg1 = g_xg + (((size_t)dir * T_LEN + sw) * B_SZ + b1) * G_SZ;
        #pragma unroll
        for (int nt = 0; nt < 8; nt++) {
            const int g = gb + nt * 8;
            const float2 bias = *(const float2*)(bs + g);
            *(float2*)(xg0 + g) = make_float2(acc[nt][0] + bias.x,
                                              acc[nt][1] + bias.y);
            *(float2*)(xg1 + g) = make_float2(acc[nt][2] + bias.x,
                                              acc[nt][3] + bias.y);
        }
    }
}

// ---------------------------------------------------------------------------
// Persistent bidirectional LSTM — R15 champion core, unchanged except the
// barrier wait: lanes 0-3 each poll ONE spread counter concurrently (wait =
// max of 4 L2 round trips instead of their sum). Happens-before composes:
// producer release-RED -> lane-q acquire-LD -> __syncthreads -> all threads.
// ---------------------------------------------------------------------------
#define WS_U2   16384                        // 8*64*32 uint2 (131072 B)
#define PS_OFF  (WS_U2 * 2)
#define PSW     2432                         // 32 rows * stride 76
#define SMEM_BYTES (WS_U2 * 8 + 8 * PSW * 4) // 208896

__global__ __launch_bounds__(256, 1)
void lstm_persist_kernel(float* __restrict__ out, int write_hc)
{
    extern __shared__ float sm[];
    uint2* ws = (uint2*)sm;
    float* ps = sm + PS_OFF;

    const int dir = blockIdx.x >> 6;
    const int ct  = blockIdx.x & 63;
    const int tid = threadIdx.x;
    const int w   = tid >> 5;
    const int L   = tid & 31;

    {   // load W_hh fp16 slice into smem (once)
        const uint2* src = g_WhhB + ((size_t)(dir * 64 + ct) << 14);
        for (int i = tid; i < WS_U2; i += 256) ws[i] = src[i];
    }

    int bb[2], ul[2];
    #pragma unroll
    for (int p = 0; p < 2; p++) {
        const int cid = tid + (p << 8);
        bb[p] = cid >> 4;
        ul[p] = cid & 15;
    }
    float creg[2] = {0.0f, 0.0f};

    const size_t OUT_HC0 = (size_t)B_SZ * T_LEN * 2 * H_SZ;
    const size_t OUT_HC1 = OUT_HC0 + (size_t)B_SZ * 2 * H_SZ;
    unsigned spin_limit = 2000000u;          // bounded: ~1.2s worst case

    __syncthreads();

    // prologue: prefetch xg for s=0
    float4 xgn[2];
    #pragma unroll
    for (int p = 0; p < 2; p++)
        xgn[p] = __ldcg((const float4*)(g_xg
                 + ((size_t)dir * T_LEN * B_SZ + bb[p]) * G_SZ
                 + (ct << 6) + (ul[p] << 2)));

    for (int s = 0; s < T_LEN; s++) {
        const int buf  = s & 1;
        const int nbuf = buf ^ 1;

        const float4 xgv0 = xgn[0];
        const float4 xgv1 = xgn[1];

        if (s > 0) {
            float acc[2][8][4];
            #pragma unroll
            for (int mt = 0; mt < 2; mt++)
                #pragma unroll
                for (int nt = 0; nt < 8; nt++)
                    #pragma unroll
                    for (int i = 0; i < 4; i++) acc[mt][nt][i] = 0.0f;

            const uint4* afb = (const uint4*)g_hfragH
                               + ((size_t)(buf * 2 + dir) * 2) * (64 * 32);
            const int kk0 = w << 3;

            // depth-2 pipelined A-fragment loads
            uint4 A[2][2];   // [stage][mt]
            #pragma unroll
            for (int st = 0; st < 2; st++)
                #pragma unroll
                for (int mt = 0; mt < 2; mt++)
                    A[st][mt] = __ldcg(afb + ((size_t)mt * 64 + kk0 + st) * 32 + L);

            #pragma unroll
            for (int i = 0; i < 8; i++) {
                const int st = i & 1;
                const int kk = kk0 + i;
                #pragma unroll
                for (int nt = 0; nt < 8; nt++) {
                    const uint2 wh = ws[((nt << 6) + kk) * 32 + L];
                    #pragma unroll
                    for (int mt = 0; mt < 2; mt++)
                        mma_f16(acc[mt][nt], A[st][mt].x, A[st][mt].y,
                                A[st][mt].z, A[st][mt].w, wh.x, wh.y);
                }
                if (i + 2 < 8) {
                    #pragma unroll
                    for (int mt = 0; mt < 2; mt++)
                        A[st][mt] = __ldcg(afb + ((size_t)mt * 64 + kk0 + i + 2) * 32
                                           + L);
                }
            }

            float* psw = ps + w * PSW;
            const int r  = L >> 2;
            const int g2 = (L & 3) * 2;
            #pragma unroll
            for (int mt = 0; mt < 2; mt++)
                #pragma unroll
                for (int nt = 0; nt < 8; nt++) {
                    const int row = mt * 16 + r;
                    const int g   = nt * 8 + g2;
                    *(float2*)&psw[row * 76 + g] =
                        make_float2(acc[mt][nt][0], acc[mt][nt][1]);
                    *(float2*)&psw[(row + 8) * 76 + g] =
                        make_float2(acc[mt][nt][2], acc[mt][nt][3]);
                }
        }
        __syncthreads();

        const int tphys = dir ? (T_LEN - 1 - s) : s;
        #pragma unroll
        for (int p = 0; p < 2; p++) {
            const int b = bb[p];
            const int u = ul[p];
            const int j = (ct << 4) + u;
            const float4 xgv = p ? xgv1 : xgv0;

            float4 v = make_float4(0.f, 0.f, 0.f, 0.f);
            if (s > 0) {
                #pragma unroll
                for (int ww = 0; ww < 8; ww++) {
                    const float4 q = *(const float4*)&ps[ww * PSW + b * 76 + u * 4];
                    v.x += q.x; v.y += q.y; v.z += q.z; v.w += q.w;
                }
            }

            const float iv = sigm(v.x + xgv.x);
            const float fv = sigm(v.y + xgv.y);
            const float gv = ftanh(v.z + xgv.z);
            const float ov = sigm(v.w + xgv.w);
            const float cc = fv * creg[p] + iv * gv;
            creg[p] = cc;
            const float h = ov * ftanh(cc);

            out[((size_t)b * T_LEN + tphys) * (2 * H_SZ) + (size_t)dir * H_SZ + j] = h;
            if (write_hc && s == T_LEN - 1) {
                out[OUT_HC0 + ((size_t)b * 2 + dir) * H_SZ + j] = h;
                out[OUT_HC1 + ((size_t)b * 2 + dir) * H_SZ + j] = cc;
            }

            const float hn = __shfl_down_sync(0xffffffffu, h, 1);
            if ((u & 1) == 0) {
                const unsigned hi = pack_h2(h, hn);
                const int mt    = b >> 4;
                const int rowin = b & 15;
                const int reg   = (rowin >> 3) + ((u >> 3) << 1);
                const int lane2 = (rowin & 7) * 4 + ((u & 7) >> 1);
                g_hfragH[(((size_t)(nbuf * 2 + dir) * 2 + mt) * 64 + ct) * 128
                         + lane2 * 4 + reg] = hi;
            }
        }

        // prefetch xg for step s+1 BEFORE the barrier (in flight during wait)
        if (s + 1 < T_LEN) {
            const size_t xgb1 = ((size_t)dir * T_LEN + (s + 1)) * B_SZ * G_SZ;
            #pragma unroll
            for (int p = 0; p < 2; p++)
                xgn[p] = __ldcg((const float4*)(g_xg + xgb1
                         + (size_t)bb[p] * G_SZ + (ct << 6) + (ul[p] << 2)));
        }

        // flat per-direction grid barrier: tid0 arrives, lanes 0-3 poll one
        // counter each concurrently (wait = max, not sum). Bounded spins.
        __syncthreads();
        if (tid == 0) {
            unsigned* ctr = &g_arr[(dir * 4 + (ct & 3)) * 32];
            asm volatile("red.release.gpu.global.add.u32 [%0], 1;"
                         :: "l"(ctr) : "memory");
        }
        if (tid < 4) {
            const unsigned tgt = (unsigned)(s + 1) * 16;
            unsigned it = 0;
            for (;;) {
                unsigned vv;
                asm volatile("ld.acquire.gpu.global.u32 %0, [%1];"
                             : "=r"(vv) : "l"(&g_arr[(dir * 4 + tid) * 32])
                             : "memory");
                if (vv >= tgt) break;
                if (++it >= spin_limit) { spin_limit = 0; break; }
            }
        }
        __syncthreads();
    }
}

// ---------------------------------------------------------------------------
extern "C" void kernel_launch(void* const* d_in, const int* in_sizes, int n_in,
                              void* d_out, int out_size)
{
    const float* x     = (const float*)d_in[0];
    const float* Wf_ih = (const float*)d_in[1];
    const float* Wf_hh = (const float*)d_in[2];
    const float* bf_ih = (const float*)d_in[3];
    const float* bf_hh = (const float*)d_in[4];
    const float* Wb_ih = (const float*)d_in[5];
    const float* Wb_hh = (const float*)d_in[6];
    const float* bb_ih = (const float*)d_in[7];
    const float* bb_hh = (const float*)d_in[8];
    float* out = (float*)d_out;

    static int smem_set = 0;
    if (!smem_set) {
        cudaFuncSetAttribute(lstm_persist_kernel,
                             cudaFuncAttributeMaxDynamicSharedMemorySize,
                             SMEM_BYTES);
        cudaFuncSetAttribute(input_gemm_mma_kernel,
                             cudaFuncAttributeMaxDynamicSharedMemorySize,
                             GEMM_SMEM);
        smem_set = 1;
    }

    // one fused prep launch: W packs + x pack + bias sums + barrier init
    prep_kernel<<<16417, 256>>>(Wf_hh, Wb_hh, Wf_ih, Wb_ih,
                                bf_ih, bf_hh, bb_ih, bb_hh, x);

    input_gemm_mma_kernel<<<dim3(8, 64, 2), 256, GEMM_SMEM>>>();

    const long long full = (long long)B_SZ * T_LEN * 2 * H_SZ
                         + 2LL * B_SZ * 2 * H_SZ;
    const int write_hc = ((long long)out_size >= full) ? 1 : 0;

    lstm_persist_kernel<<<NCTA, 256, SMEM_BYTES>>>(out, write_hc);
}